// round 9
// baseline (speedup 1.0000x reference)
#include <cuda_runtime.h>
#include <cuda_fp16.h>
#include <math.h>
#include <stdint.h>

#define N_NODES 50000
#define N_EDGES 800000
#define N_GRAPHS 100

// ---------------- device scratch (no allocation allowed; 16B aligned) ----------------
__device__ __align__(16) int    d_cnt[N_NODES];      // stays 0 between calls (re-zeroed by pool_mlp)
__device__ __align__(16) float  d_dinv[N_NODES];
__device__ __align__(16) int    d_off[N_NODES];
__device__ __align__(16) int    d_cursor[N_NODES];
__device__ __align__(16) int    d_src[N_EDGES];
__device__ int d_gcur;                               // stays 0 between calls
__device__ __align__(16) __half d_t[(size_t)N_NODES * 128];   // fp16 gather buffer
__device__ __align__(16) float  d_h[(size_t)N_NODES * 128];

// ---------------- packed f32x2 helpers ----------------
__device__ __forceinline__ unsigned long long pk2(float x) {
    unsigned long long r;
    asm("mov.b64 %0, {%1, %1};" : "=l"(r) : "r"(__float_as_uint(x)));
    return r;
}
#define FMA2(acc, a, b) \
    asm("fma.rn.f32x2 %0, %1, %2, %0;" : "+l"(acc) : "l"(a), "l"(b))
#define MUL2(d, a, b) \
    asm("mul.rn.f32x2 %0, %1, %2;" : "=l"(d) : "l"(a), "l"(b))

__device__ __forceinline__ uint32_t h2_from_u64(unsigned long long v) {
    float2 f;
    asm("mov.b64 {%0, %1}, %2;" : "=f"(f.x), "=f"(f.y) : "l"(v));
    __half2 h = __float22half2_rn(f);
    return *reinterpret_cast<uint32_t*>(&h);
}

// ---------------- CSR build (scan-free) ----------------
__global__ void count_kernel(const int* __restrict__ col, int* __restrict__ cnt) {
    int e2 = blockIdx.x * blockDim.x + threadIdx.x;
    int e = e2 * 2;
    if (e + 1 < N_EDGES) {
        int2 c = *reinterpret_cast<const int2*>(col + e);
        if ((unsigned)c.x < N_NODES) atomicAdd(cnt + c.x, 1);
        if ((unsigned)c.y < N_NODES) atomicAdd(cnt + c.y, 1);
    } else if (e < N_EDGES) {
        unsigned c = (unsigned)col[e];
        if (c < N_NODES) atomicAdd(cnt + c, 1);
    }
}

__global__ void assign_kernel(const int* __restrict__ cnt, int* __restrict__ off,
                              int* __restrict__ cursor, float* __restrict__ dinv,
                              int* __restrict__ gcur) {
    __shared__ int ws[32];
    __shared__ int s_base;
    int i = blockIdx.x * 1024 + threadIdx.x;
    int lane = threadIdx.x & 31, wid = threadIdx.x >> 5;
    int v = (i < N_NODES) ? cnt[i] : 0;
    int x = v;
    #pragma unroll
    for (int d = 1; d < 32; d <<= 1) {
        int y = __shfl_up_sync(0xffffffffu, x, d);
        if (lane >= d) x += y;
    }
    if (lane == 31) ws[wid] = x;
    __syncthreads();
    if (wid == 0) {
        int s = ws[lane];
        #pragma unroll
        for (int d = 1; d < 32; d <<= 1) {
            int y = __shfl_up_sync(0xffffffffu, s, d);
            if (lane >= d) s += y;
        }
        ws[lane] = s;
        if (lane == 31) s_base = atomicAdd(gcur, s);
    }
    __syncthreads();
    int excl = s_base + (wid ? ws[wid - 1] : 0) + x - v;
    if (i < N_NODES) {
        off[i] = excl;
        cursor[i] = excl;
        dinv[i] = rsqrtf((float)(v + 1));
    }
}

__global__ void fill_kernel(const int* __restrict__ row,
                            const int* __restrict__ col,
                            int* __restrict__ cursor, int* __restrict__ src) {
    int e2 = blockIdx.x * blockDim.x + threadIdx.x;
    int e = e2 * 2;
    if (e + 1 < N_EDGES) {
        int2 c = *reinterpret_cast<const int2*>(col + e);
        int2 r = *reinterpret_cast<const int2*>(row + e);
        if ((unsigned)c.x < N_NODES) {
            int pos = atomicAdd(cursor + c.x, 1);
            if ((unsigned)pos < N_EDGES) src[pos] = r.x;
        }
        if ((unsigned)c.y < N_NODES) {
            int pos = atomicAdd(cursor + c.y, 1);
            if ((unsigned)pos < N_EDGES) src[pos] = r.y;
        }
    } else if (e < N_EDGES) {
        unsigned c = (unsigned)col[e];
        if (c < N_NODES) {
            int pos = atomicAdd(cursor + c, 1);
            if ((unsigned)pos < N_EDGES) src[pos] = row[e];
        }
    }
}

// ---------------- GEMM: T[v] = half( scale * (A[v] @ W) ) ----------------
// BM=128 rows/CTA, 128 threads, W resident in smem, A streamed in BK=32 chunks.
// SCALE_DINV: multiply by dinv[row] in epilogue (layers 2/3); layer 1 stores raw.
template <int NOUT, bool SCALE_DINV>
__global__ void __launch_bounds__(128, 2)
gemm_kernel(const float* __restrict__ A, const float* __restrict__ W,
            const float* __restrict__ dinv, __half* __restrict__ T) {
    constexpr int RT = (NOUT == 128) ? 16 : 8;   // rows per thread
    constexpr int CG = NOUT / 8;                 // col groups
    extern __shared__ __align__(16) float smem[];
    float* Ws = smem;                            // [128][NOUT]
    float* As = smem + 128 * NOUT;               // [32][128] k-major chunk
    int tid = threadIdx.x;
    int row0 = blockIdx.x * 128;

    // load W once
    for (int i = tid; i < 128 * NOUT / 4; i += 128)
        reinterpret_cast<float4*>(Ws)[i] = reinterpret_cast<const float4*>(W)[i];

    int tx = tid % CG, ty = tid / CG;
    int c0 = tx * 8, r0 = ty * RT;

    unsigned long long acc[RT][4];
    #pragma unroll
    for (int i = 0; i < RT; i++)
        #pragma unroll
        for (int p = 0; p < 4; p++) acc[i][p] = 0ULL;

    // A chunk prefetch: thread owns row (row0+tid), loads its 32 k-values
    const float* arow = A + (size_t)(row0 + tid) * 128;
    bool rv = (row0 + tid) < N_NODES;
    float4 pre[8];
    #pragma unroll
    for (int j = 0; j < 8; j++)
        pre[j] = rv ? *reinterpret_cast<const float4*>(arow + j * 4)
                    : make_float4(0.f, 0.f, 0.f, 0.f);

    #pragma unroll
    for (int ch = 0; ch < 4; ch++) {
        __syncthreads();    // As free (first iter also orders W writes)
        #pragma unroll
        for (int j = 0; j < 8; j++) {
            int kb = j * 4;
            As[(kb + 0) * 128 + tid] = pre[j].x;
            As[(kb + 1) * 128 + tid] = pre[j].y;
            As[(kb + 2) * 128 + tid] = pre[j].z;
            As[(kb + 3) * 128 + tid] = pre[j].w;
        }
        __syncthreads();
        if (ch < 3) {
            const float* nsrc = arow + (ch + 1) * 32;
            #pragma unroll
            for (int j = 0; j < 8; j++)
                pre[j] = rv ? *reinterpret_cast<const float4*>(nsrc + j * 4)
                            : make_float4(0.f, 0.f, 0.f, 0.f);
        }
        const float* wch = Ws + ch * 32 * NOUT + c0;
        #pragma unroll 4
        for (int k = 0; k < 32; k++) {
            const float* ar = As + k * 128 + r0;
            unsigned long long ap[RT];
            #pragma unroll
            for (int q = 0; q < RT / 4; q++) {
                float4 a4 = *reinterpret_cast<const float4*>(ar + q * 4);
                ap[q * 4 + 0] = pk2(a4.x);
                ap[q * 4 + 1] = pk2(a4.y);
                ap[q * 4 + 2] = pk2(a4.z);
                ap[q * 4 + 3] = pk2(a4.w);
            }
            const float* wr = wch + k * NOUT;
            ulonglong2 u0 = *reinterpret_cast<const ulonglong2*>(wr);
            ulonglong2 u1 = *reinterpret_cast<const ulonglong2*>(wr + 4);
            #pragma unroll
            for (int i = 0; i < RT; i++) {
                FMA2(acc[i][0], ap[i], u0.x);
                FMA2(acc[i][1], ap[i], u0.y);
                FMA2(acc[i][2], ap[i], u1.x);
                FMA2(acc[i][3], ap[i], u1.y);
            }
        }
    }

    // epilogue: (optionally) scale by dinv, convert to half, store 16B per row
    #pragma unroll
    for (int i = 0; i < RT; i++) {
        int r = row0 + r0 + i;
        if (r < N_NODES) {
            uint4 o;
            if (SCALE_DINV) {
                unsigned long long dvp = pk2(dinv[r]);
                unsigned long long m;
                MUL2(m, acc[i][0], dvp); o.x = h2_from_u64(m);
                MUL2(m, acc[i][1], dvp); o.y = h2_from_u64(m);
                MUL2(m, acc[i][2], dvp); o.z = h2_from_u64(m);
                MUL2(m, acc[i][3], dvp); o.w = h2_from_u64(m);
            } else {
                o.x = h2_from_u64(acc[i][0]);
                o.y = h2_from_u64(acc[i][1]);
                o.z = h2_from_u64(acc[i][2]);
                o.w = h2_from_u64(acc[i][3]);
            }
            *reinterpret_cast<uint4*>(T + (size_t)r * NOUT + c0) = o;
        }
    }
}

// ---------------- aggregation ----------------
// SRC_SCALE=false: h[v] = relu(dinv[v]*(t[v] + sum t[src]) + b)        (t pre-scaled)
// SRC_SCALE=true : h[v] = relu(dinv[v]*(dinv[v]*t[v] + sum dinv[s]*t[s]) + b)  (t raw)
template <int F, bool SRC_SCALE>
__global__ void agg_kernel(const __half* __restrict__ T,
                           const int* __restrict__ off,
                           const int* __restrict__ cnt,
                           const float* __restrict__ dinv,
                           const float* __restrict__ bias,
                           float* __restrict__ H,
                           const int* __restrict__ src) {
    constexpr int V = F / 32;                 // 4 or 2 halves per lane
    int warp = threadIdx.x >> 5, lane = threadIdx.x & 31;
    int v = blockIdx.x * (blockDim.x >> 5) + warp;
    if (v >= N_NODES) return;
    int f0 = lane * V;
    float dv = dinv[v];
    float acc[V];
    {
        const __half* tv = T + (size_t)v * F + f0;
        float selfs = SRC_SCALE ? dv : 1.0f;
        if (V == 4) {
            uint2 q = *reinterpret_cast<const uint2*>(tv);
            float2 a = __half22float2(*reinterpret_cast<const __half2*>(&q.x));
            float2 b = __half22float2(*reinterpret_cast<const __half2*>(&q.y));
            acc[0] = selfs * a.x; acc[1] = selfs * a.y;
            acc[2] = selfs * b.x; acc[3] = selfs * b.y;
        } else {
            uint32_t q = *reinterpret_cast<const uint32_t*>(tv);
            float2 a = __half22float2(*reinterpret_cast<const __half2*>(&q));
            acc[0] = selfs * a.x; acc[1] = selfs * a.y;
        }
    }
    int e0 = off[v], e1 = e0 + cnt[v];
    #pragma unroll 4
    for (int e = e0; e < e1; e++) {
        int s = src[e];
        float ds = SRC_SCALE ? dinv[s] : 1.0f;
        const __half* ts = T + (size_t)s * F + f0;
        if (V == 4) {
            uint2 q = *reinterpret_cast<const uint2*>(ts);
            float2 a = __half22float2(*reinterpret_cast<const __half2*>(&q.x));
            float2 b = __half22float2(*reinterpret_cast<const __half2*>(&q.y));
            if (SRC_SCALE) {
                acc[0] = fmaf(ds, a.x, acc[0]); acc[1] = fmaf(ds, a.y, acc[1]);
                acc[2] = fmaf(ds, b.x, acc[2]); acc[3] = fmaf(ds, b.y, acc[3]);
            } else {
                acc[0] += a.x; acc[1] += a.y; acc[2] += b.x; acc[3] += b.y;
            }
        } else {
            uint32_t q = *reinterpret_cast<const uint32_t*>(ts);
            float2 a = __half22float2(*reinterpret_cast<const __half2*>(&q));
            if (SRC_SCALE) {
                acc[0] = fmaf(ds, a.x, acc[0]); acc[1] = fmaf(ds, a.y, acc[1]);
            } else {
                acc[0] += a.x; acc[1] += a.y;
            }
        }
    }
    float* hv = H + (size_t)v * F + f0;
    #pragma unroll
    for (int i = 0; i < V; i++) {
        float o = dv * acc[i] + bias[f0 + i];
        hv[i] = fmaxf(o, 0.f);
    }
}

// ---------------- pooling + MLP (+ cleanup of cnt/gcur for next call) ----------------
__device__ __forceinline__ int lb32(const int* __restrict__ b, int n, int key) {
    int lo = 0, hi = n;
    while (lo < hi) {
        int mid = (lo + hi) >> 1;
        if (b[mid] < key) lo = mid + 1; else hi = mid;
    }
    return lo;
}

__global__ void pool_mlp_kernel(const float* __restrict__ H,
                                const int* __restrict__ batch,
                                const float* __restrict__ Wf1, const float* __restrict__ bf1,
                                const float* __restrict__ Wf2, const float* __restrict__ bf2,
                                float* __restrict__ out,
                                int* __restrict__ cnt, int* __restrict__ gcur) {
    __shared__ float partial[256];
    __shared__ float pooled[64];
    __shared__ float hid[32];
    int g = blockIdx.x;
    int t = threadIdx.x;
    for (int i = g * 256 + t; i < N_NODES; i += N_GRAPHS * 256) cnt[i] = 0;
    if (g == 0 && t == 0) *gcur = 0;

    int start = lb32(batch, N_NODES, g);
    int end   = lb32(batch, N_NODES, g + 1);
    int n = end - start;
    int feat = t & 63;
    int strip = t >> 6;
    float s = 0.f;
    for (int i = start + strip; i < end; i += 4)
        s += H[(size_t)i * 64 + feat];
    partial[t] = s;
    __syncthreads();
    if (t < 64) {
        float tot = partial[t] + partial[t + 64] + partial[t + 128] + partial[t + 192];
        pooled[t] = tot / fmaxf((float)n, 1.0f);
    }
    __syncthreads();
    if (t < 32) {
        float a = bf1[t];
        #pragma unroll 8
        for (int k = 0; k < 64; k++) a += pooled[k] * Wf1[k * 32 + t];
        hid[t] = fmaxf(a, 0.f);
    }
    __syncthreads();
    if (t < 10) {
        float a = bf2[t];
        #pragma unroll
        for (int k = 0; k < 32; k++) a += hid[k] * Wf2[k * 10 + t];
        out[g * 10 + t] = a;
    }
}

// ---------------- launch ----------------
extern "C" void kernel_launch(void* const* d_in, const int* in_sizes, int n_in,
                              void* d_out, int out_size) {
    const float* x     = (const float*)d_in[0];
    const int*   ei    = (const int*)d_in[1];     // int32 (JAX x64 disabled)
    const int*   batch = (const int*)d_in[2];
    const float* W1 = (const float*)d_in[3];
    const float* b1 = (const float*)d_in[4];
    const float* W2 = (const float*)d_in[5];
    const float* b2 = (const float*)d_in[6];
    const float* W3 = (const float*)d_in[7];
    const float* b3 = (const float*)d_in[8];
    const float* Wf1 = (const float*)d_in[9];
    const float* bf1 = (const float*)d_in[10];
    const float* Wf2 = (const float*)d_in[11];
    const float* bf2 = (const float*)d_in[12];
    float* out = (float*)d_out;

    const int* row = ei;
    const int* col = ei + N_EDGES;

    int *p_cnt, *p_off, *p_cursor, *p_src, *p_gcur;
    float *p_dinv, *p_h;
    __half* p_t;
    cudaGetSymbolAddress((void**)&p_cnt,    d_cnt);
    cudaGetSymbolAddress((void**)&p_off,    d_off);
    cudaGetSymbolAddress((void**)&p_cursor, d_cursor);
    cudaGetSymbolAddress((void**)&p_src,    d_src);
    cudaGetSymbolAddress((void**)&p_gcur,   d_gcur);
    cudaGetSymbolAddress((void**)&p_dinv,   d_dinv);
    cudaGetSymbolAddress((void**)&p_t,      d_t);
    cudaGetSymbolAddress((void**)&p_h,      d_h);

    // side stream + fork/join events (host objects, created once; device work
    // per call is identical and deterministic)
    static cudaStream_t s2 = nullptr;
    static cudaEvent_t evF = nullptr, evJ = nullptr;
    if (s2 == nullptr) {
        cudaStreamCreateWithFlags(&s2, cudaStreamNonBlocking);
        cudaEventCreateWithFlags(&evF, cudaEventDisableTiming);
        cudaEventCreateWithFlags(&evJ, cudaEventDisableTiming);
    }

    const int SM128 = (128 * 128 + 32 * 128) * 4;   // 80 KB
    const int SM64  = (128 * 64  + 32 * 128) * 4;   // 48 KB
    cudaFuncSetAttribute((const void*)gemm_kernel<128, false>, cudaFuncAttributeMaxDynamicSharedMemorySize, SM128);
    cudaFuncSetAttribute((const void*)gemm_kernel<128, true>,  cudaFuncAttributeMaxDynamicSharedMemorySize, SM128);
    cudaFuncSetAttribute((const void*)gemm_kernel<64, true>,   cudaFuncAttributeMaxDynamicSharedMemorySize, SM64);

    const int E2 = (N_EDGES / 2 + 255) / 256;
    const int GB = (N_NODES + 127) / 128;    // 391
    const int AGG_BLOCKS = (N_NODES + 7) / 8;

    // fork: gemm1 (no dinv dependency) runs concurrent with CSR build
    gemm_kernel<128, false><<<GB, 128, SM128>>>(x, W1, p_dinv, p_t);                 // k1 (stream 0)
    cudaEventRecord(evF, 0);
    cudaStreamWaitEvent(s2, evF, 0);
    count_kernel<<<E2, 256, 0, s2>>>(col, p_cnt);                                    // k2 (s2)
    assign_kernel<<<(N_NODES + 1023) / 1024, 1024, 0, s2>>>(p_cnt, p_off, p_cursor, p_dinv, p_gcur); // k3
    fill_kernel<<<E2, 256, 0, s2>>>(row, col, p_cursor, p_src);                      // k4
    cudaEventRecord(evJ, s2);
    cudaStreamWaitEvent(0, evJ, 0);
    // join: everything below on stream 0
    agg_kernel<128, true><<<AGG_BLOCKS, 256>>>(p_t, p_off, p_cnt, p_dinv, b1, p_h, p_src);  // k5
    gemm_kernel<128, true><<<GB, 128, SM128>>>(p_h, W2, p_dinv, p_t);                // k6 <- ncu
    agg_kernel<128, false><<<AGG_BLOCKS, 256>>>(p_t, p_off, p_cnt, p_dinv, b2, p_h, p_src); // k7
    gemm_kernel<64, true><<<GB, 128, SM64>>>(p_h, W3, p_dinv, p_t);                  // k8
    agg_kernel<64, false><<<AGG_BLOCKS, 256>>>(p_t, p_off, p_cnt, p_dinv, b3, p_h, p_src);  // k9

    pool_mlp_kernel<<<N_GRAPHS, 256>>>(p_h, batch, Wf1, bf1, Wf2, bf2, out, p_cnt, p_gcur); // k10
}

// round 10
// speedup vs baseline: 1.5511x; 1.5511x over previous
#include <cuda_runtime.h>
#include <cuda_fp16.h>
#include <math.h>
#include <stdint.h>

#define N_NODES 50000
#define N_EDGES 800000
#define N_GRAPHS 100

// ---------------- device scratch (no allocation allowed; 16B aligned) ----------------
__device__ __align__(16) int    d_cnt[N_NODES];      // stays 0 between calls (re-zeroed by pool_mlp)
__device__ __align__(16) float  d_dinv[N_NODES];
__device__ __align__(16) int    d_off[N_NODES];
__device__ __align__(16) int    d_cursor[N_NODES];
__device__ __align__(16) int    d_src[N_EDGES];
__device__ int d_gcur;                               // stays 0 between calls
__device__ __align__(16) __half d_t[(size_t)N_NODES * 128];   // fp16 gather buffer
__device__ __align__(16) __half d_hh[(size_t)N_NODES * 128];  // fp16 features

// ---------------- mma helpers ----------------
__device__ __forceinline__ uint32_t smem_u32(const void* p) {
    uint32_t a;
    asm("{ .reg .u64 t; cvta.to.shared.u64 t, %1; cvt.u32.u64 %0, t; }" : "=r"(a) : "l"(p));
    return a;
}
__device__ __forceinline__ void ldsm_x4(uint32_t& r0, uint32_t& r1, uint32_t& r2, uint32_t& r3,
                                        uint32_t addr) {
    asm volatile("ldmatrix.sync.aligned.m8n8.x4.shared.b16 {%0,%1,%2,%3}, [%4];"
                 : "=r"(r0), "=r"(r1), "=r"(r2), "=r"(r3) : "r"(addr));
}
__device__ __forceinline__ void ldsm_x4_t(uint32_t& r0, uint32_t& r1, uint32_t& r2, uint32_t& r3,
                                          uint32_t addr) {
    asm volatile("ldmatrix.sync.aligned.m8n8.x4.trans.shared.b16 {%0,%1,%2,%3}, [%4];"
                 : "=r"(r0), "=r"(r1), "=r"(r2), "=r"(r3) : "r"(addr));
}
__device__ __forceinline__ void mma16816(float* c, const uint32_t* a, uint32_t b0, uint32_t b1) {
    asm volatile("mma.sync.aligned.m16n8k16.row.col.f32.f16.f16.f32 "
                 "{%0,%1,%2,%3}, {%4,%5,%6,%7}, {%8,%9}, {%0,%1,%2,%3};"
                 : "+f"(c[0]), "+f"(c[1]), "+f"(c[2]), "+f"(c[3])
                 : "r"(a[0]), "r"(a[1]), "r"(a[2]), "r"(a[3]), "r"(b0), "r"(b1));
}

// ---------------- CSR build (scan-free) ----------------
__global__ void count_kernel(const int* __restrict__ col, int* __restrict__ cnt) {
    int e2 = blockIdx.x * blockDim.x + threadIdx.x;
    int e = e2 * 2;
    if (e + 1 < N_EDGES) {
        int2 c = *reinterpret_cast<const int2*>(col + e);
        if ((unsigned)c.x < N_NODES) atomicAdd(cnt + c.x, 1);
        if ((unsigned)c.y < N_NODES) atomicAdd(cnt + c.y, 1);
    } else if (e < N_EDGES) {
        unsigned c = (unsigned)col[e];
        if (c < N_NODES) atomicAdd(cnt + c, 1);
    }
}

__global__ void assign_kernel(const int* __restrict__ cnt, int* __restrict__ off,
                              int* __restrict__ cursor, float* __restrict__ dinv,
                              int* __restrict__ gcur) {
    __shared__ int ws[32];
    __shared__ int s_base;
    int i = blockIdx.x * 1024 + threadIdx.x;
    int lane = threadIdx.x & 31, wid = threadIdx.x >> 5;
    int v = (i < N_NODES) ? cnt[i] : 0;
    int x = v;
    #pragma unroll
    for (int d = 1; d < 32; d <<= 1) {
        int y = __shfl_up_sync(0xffffffffu, x, d);
        if (lane >= d) x += y;
    }
    if (lane == 31) ws[wid] = x;
    __syncthreads();
    if (wid == 0) {
        int s = ws[lane];
        #pragma unroll
        for (int d = 1; d < 32; d <<= 1) {
            int y = __shfl_up_sync(0xffffffffu, s, d);
            if (lane >= d) s += y;
        }
        ws[lane] = s;
        if (lane == 31) s_base = atomicAdd(gcur, s);
    }
    __syncthreads();
    int excl = s_base + (wid ? ws[wid - 1] : 0) + x - v;
    if (i < N_NODES) {
        off[i] = excl;
        cursor[i] = excl;
        dinv[i] = rsqrtf((float)(v + 1));
    }
}

__global__ void fill_kernel(const int* __restrict__ row,
                            const int* __restrict__ col,
                            int* __restrict__ cursor, int* __restrict__ src) {
    int e2 = blockIdx.x * blockDim.x + threadIdx.x;
    int e = e2 * 2;
    if (e + 1 < N_EDGES) {
        int2 c = *reinterpret_cast<const int2*>(col + e);
        int2 r = *reinterpret_cast<const int2*>(row + e);
        if ((unsigned)c.x < N_NODES) {
            int pos = atomicAdd(cursor + c.x, 1);
            if ((unsigned)pos < N_EDGES) src[pos] = r.x;
        }
        if ((unsigned)c.y < N_NODES) {
            int pos = atomicAdd(cursor + c.y, 1);
            if ((unsigned)pos < N_EDGES) src[pos] = r.y;
        }
    } else if (e < N_EDGES) {
        unsigned c = (unsigned)col[e];
        if (c < N_NODES) {
            int pos = atomicAdd(cursor + c, 1);
            if ((unsigned)pos < N_EDGES) src[pos] = row[e];
        }
    }
}

// ---------------- HMMA GEMM: T[v] = half( dinv[v] * (A[v] @ W) ) ----------------
// BM=128 rows/CTA, 256 threads (8 warps). A,W fp16 in smem, XOR-swizzled 16B chunks.
// Warp grid 4x2: warp tile 32 x (NOUT/2). K = 8 x k16.
// A32: A is fp32 (layer 1, x); else fp16 (H from agg).
template <int NOUT, bool A32>
__global__ void __launch_bounds__(256, 2)
gemm_mma_kernel(const void* __restrict__ Ain, const float* __restrict__ W,
                const float* __restrict__ dinv, __half* __restrict__ T) {
    extern __shared__ __align__(16) __half smem[];
    __half* sA = smem;                 // [128][128] swizzled
    __half* sW = smem + 128 * 128;     // [128][NOUT] swizzled
    constexpr int WCH = NOUT / 8;      // 16B chunks per W row
    int tid = threadIdx.x, lane = tid & 31, warp = tid >> 5;
    int row0 = blockIdx.x * 128;

    // ---- load W fp32 -> fp16, swizzled
    for (int i = tid; i < 128 * WCH; i += 256) {
        int r = i / WCH, cb = i % WCH;
        const float* wp = W + (size_t)r * NOUT + cb * 8;
        float4 w0 = *reinterpret_cast<const float4*>(wp);
        float4 w1 = *reinterpret_cast<const float4*>(wp + 4);
        uint4 o;
        __half2 h;
        h = __floats2half2_rn(w0.x, w0.y); o.x = *reinterpret_cast<uint32_t*>(&h);
        h = __floats2half2_rn(w0.z, w0.w); o.y = *reinterpret_cast<uint32_t*>(&h);
        h = __floats2half2_rn(w1.x, w1.y); o.z = *reinterpret_cast<uint32_t*>(&h);
        h = __floats2half2_rn(w1.z, w1.w); o.w = *reinterpret_cast<uint32_t*>(&h);
        int sc = cb ^ (r & 7);
        if (NOUT == 64) sc &= 7;
        *reinterpret_cast<uint4*>(sW + (size_t)r * NOUT + sc * 8) = o;
    }
    // ---- load A rows (thread pair per row; 8 chunks each), swizzled
    {
        int r = tid >> 1, part = tid & 1;
        int gr = row0 + r;
        bool rv = gr < N_NODES;
        #pragma unroll
        for (int j = 0; j < 8; j++) {
            int cb = part * 8 + j;
            uint4 o;
            if (A32) {
                const float* ap = (const float*)Ain + (size_t)gr * 128 + cb * 8;
                float4 a0 = rv ? *reinterpret_cast<const float4*>(ap)
                               : make_float4(0.f, 0.f, 0.f, 0.f);
                float4 a1 = rv ? *reinterpret_cast<const float4*>(ap + 4)
                               : make_float4(0.f, 0.f, 0.f, 0.f);
                __half2 h;
                h = __floats2half2_rn(a0.x, a0.y); o.x = *reinterpret_cast<uint32_t*>(&h);
                h = __floats2half2_rn(a0.z, a0.w); o.y = *reinterpret_cast<uint32_t*>(&h);
                h = __floats2half2_rn(a1.x, a1.y); o.z = *reinterpret_cast<uint32_t*>(&h);
                h = __floats2half2_rn(a1.z, a1.w); o.w = *reinterpret_cast<uint32_t*>(&h);
            } else {
                const __half* ap = (const __half*)Ain + (size_t)gr * 128 + cb * 8;
                o = rv ? *reinterpret_cast<const uint4*>(ap)
                       : make_uint4(0u, 0u, 0u, 0u);
            }
            *reinterpret_cast<uint4*>(sA + (size_t)r * 128 + (cb ^ (r & 7)) * 8) = o;
        }
    }
    __syncthreads();

    constexpr int NT8 = NOUT / 16;     // n8 tiles per warp: 8 or 4
    int wm = warp & 3, wn = warp >> 2;
    int rw = wm * 32;                  // warp row base
    int nw = wn * (NOUT / 2);          // warp col base

    float acc[2][NT8][4];
    #pragma unroll
    for (int m = 0; m < 2; m++)
        #pragma unroll
        for (int j = 0; j < NT8; j++)
            #pragma unroll
            for (int q = 0; q < 4; q++) acc[m][j][q] = 0.f;

    int lrow = (lane & 7) + ((lane & 8) ? 8 : 0);
    int lcol = (lane & 16) ? 8 : 0;

    #pragma unroll
    for (int kk = 0; kk < 128; kk += 16) {
        uint32_t a[2][4];
        #pragma unroll
        for (int m = 0; m < 2; m++) {
            int r_ = rw + m * 16 + lrow;
            int c_ = kk + lcol;
            ldsm_x4(a[m][0], a[m][1], a[m][2], a[m][3],
                    smem_u32(sA + (size_t)r_ * 128 + (((c_ >> 3) ^ (r_ & 7)) << 3)));
        }
        uint32_t b[NT8][2];
        #pragma unroll
        for (int j = 0; j < NT8 / 2; j++) {
            int kr = kk + lrow;
            int nc = nw + j * 16 + lcol;
            int sc = (nc >> 3) ^ (kr & 7);
            if (NOUT == 64) sc &= 7;
            uint32_t t0, t1, t2, t3;
            ldsm_x4_t(t0, t1, t2, t3, smem_u32(sW + (size_t)kr * NOUT + (sc << 3)));
            b[2 * j][0] = t0; b[2 * j][1] = t1;
            b[2 * j + 1][0] = t2; b[2 * j + 1][1] = t3;
        }
        #pragma unroll
        for (int m = 0; m < 2; m++)
            #pragma unroll
            for (int j = 0; j < NT8; j++)
                mma16816(acc[m][j], a[m], b[j][0], b[j][1]);
    }

    // epilogue: scale by dinv, fp16 store
    #pragma unroll
    for (int m = 0; m < 2; m++) {
        int ro = rw + m * 16 + (lane >> 2);
        int r1 = row0 + ro, r2 = r1 + 8;
        float dv1 = (r1 < N_NODES) ? dinv[r1] : 0.f;
        float dv2 = (r2 < N_NODES) ? dinv[r2] : 0.f;
        #pragma unroll
        for (int j = 0; j < NT8; j++) {
            int c = nw + j * 8 + (lane & 3) * 2;
            if (r1 < N_NODES) {
                __half2 h = __floats2half2_rn(acc[m][j][0] * dv1, acc[m][j][1] * dv1);
                *reinterpret_cast<__half2*>(T + (size_t)r1 * NOUT + c) = h;
            }
            if (r2 < N_NODES) {
                __half2 h = __floats2half2_rn(acc[m][j][2] * dv2, acc[m][j][3] * dv2);
                *reinterpret_cast<__half2*>(T + (size_t)r2 * NOUT + c) = h;
            }
        }
    }
}

// ---------------- aggregation: h[v] = relu(dinv[v]*(t[v] + sum_in t[src]) + b), fp16 out ----------------
template <int F>
__global__ void agg_kernel(const __half* __restrict__ T,
                           const int* __restrict__ off,
                           const int* __restrict__ cnt,
                           const float* __restrict__ dinv,
                           const float* __restrict__ bias,
                           __half* __restrict__ H,
                           const int* __restrict__ src) {
    constexpr int V = F / 32;                 // 4 or 2 halves per lane
    int warp = threadIdx.x >> 5, lane = threadIdx.x & 31;
    int v = blockIdx.x * (blockDim.x >> 5) + warp;
    if (v >= N_NODES) return;
    int f0 = lane * V;
    float acc[V];
    {
        const __half* tv = T + (size_t)v * F + f0;
        if (V == 4) {
            uint2 q = *reinterpret_cast<const uint2*>(tv);
            float2 a = __half22float2(*reinterpret_cast<const __half2*>(&q.x));
            float2 b = __half22float2(*reinterpret_cast<const __half2*>(&q.y));
            acc[0] = a.x; acc[1] = a.y; acc[2] = b.x; acc[3] = b.y;
        } else {
            uint32_t q = *reinterpret_cast<const uint32_t*>(tv);
            float2 a = __half22float2(*reinterpret_cast<const __half2*>(&q));
            acc[0] = a.x; acc[1] = a.y;
        }
    }
    int e0 = off[v], e1 = e0 + cnt[v];
    #pragma unroll 4
    for (int e = e0; e < e1; e++) {
        int s = src[e];
        const __half* ts = T + (size_t)s * F + f0;
        if (V == 4) {
            uint2 q = *reinterpret_cast<const uint2*>(ts);
            float2 a = __half22float2(*reinterpret_cast<const __half2*>(&q.x));
            float2 b = __half22float2(*reinterpret_cast<const __half2*>(&q.y));
            acc[0] += a.x; acc[1] += a.y; acc[2] += b.x; acc[3] += b.y;
        } else {
            uint32_t q = *reinterpret_cast<const uint32_t*>(ts);
            float2 a = __half22float2(*reinterpret_cast<const __half2*>(&q));
            acc[0] += a.x; acc[1] += a.y;
        }
    }
    float dv = dinv[v];
    #pragma unroll
    for (int i = 0; i < V; i++)
        acc[i] = fmaxf(dv * acc[i] + bias[f0 + i], 0.f);
    __half* hv = H + (size_t)v * F + f0;
    if (V == 4) {
        uint2 o;
        __half2 h;
        h = __floats2half2_rn(acc[0], acc[1]); o.x = *reinterpret_cast<uint32_t*>(&h);
        h = __floats2half2_rn(acc[2], acc[3]); o.y = *reinterpret_cast<uint32_t*>(&h);
        *reinterpret_cast<uint2*>(hv) = o;
    } else {
        __half2 h = __floats2half2_rn(acc[0], acc[1]);
        *reinterpret_cast<__half2*>(hv) = h;
    }
}

// ---------------- pooling + MLP (+ cleanup of cnt/gcur for next call) ----------------
__device__ __forceinline__ int lb32(const int* __restrict__ b, int n, int key) {
    int lo = 0, hi = n;
    while (lo < hi) {
        int mid = (lo + hi) >> 1;
        if (b[mid] < key) lo = mid + 1; else hi = mid;
    }
    return lo;
}

__global__ void pool_mlp_kernel(const __half* __restrict__ H,
                                const int* __restrict__ batch,
                                const float* __restrict__ Wf1, const float* __restrict__ bf1,
                                const float* __restrict__ Wf2, const float* __restrict__ bf2,
                                float* __restrict__ out,
                                int* __restrict__ cnt, int* __restrict__ gcur) {
    __shared__ float partial[256];
    __shared__ float pooled[64];
    __shared__ float hid[32];
    int g = blockIdx.x;
    int t = threadIdx.x;
    for (int i = g * 256 + t; i < N_NODES; i += N_GRAPHS * 256) cnt[i] = 0;
    if (g == 0 && t == 0) *gcur = 0;

    int start = lb32(batch, N_NODES, g);
    int end   = lb32(batch, N_NODES, g + 1);
    int n = end - start;
    int feat = t & 63;
    int strip = t >> 6;
    float s = 0.f;
    for (int i = start + strip; i < end; i += 4)
        s += __half2float(H[(size_t)i * 64 + feat]);
    partial[t] = s;
    __syncthreads();
    if (t < 64) {
        float tot = partial[t] + partial[t + 64] + partial[t + 128] + partial[t + 192];
        pooled[t] = tot / fmaxf((float)n, 1.0f);
    }
    __syncthreads();
    if (t < 32) {
        float a = bf1[t];
        #pragma unroll 8
        for (int k = 0; k < 64; k++) a += pooled[k] * Wf1[k * 32 + t];
        hid[t] = fmaxf(a, 0.f);
    }
    __syncthreads();
    if (t < 10) {
        float a = bf2[t];
        #pragma unroll
        for (int k = 0; k < 32; k++) a += hid[k] * Wf2[k * 10 + t];
        out[g * 10 + t] = a;
    }
}

// ---------------- launch ----------------
extern "C" void kernel_launch(void* const* d_in, const int* in_sizes, int n_in,
                              void* d_out, int out_size) {
    const float* x     = (const float*)d_in[0];
    const int*   ei    = (const int*)d_in[1];     // int32 (JAX x64 disabled)
    const int*   batch = (const int*)d_in[2];
    const float* W1 = (const float*)d_in[3];
    const float* b1 = (const float*)d_in[4];
    const float* W2 = (const float*)d_in[5];
    const float* b2 = (const float*)d_in[6];
    const float* W3 = (const float*)d_in[7];
    const float* b3 = (const float*)d_in[8];
    const float* Wf1 = (const float*)d_in[9];
    const float* bf1 = (const float*)d_in[10];
    const float* Wf2 = (const float*)d_in[11];
    const float* bf2 = (const float*)d_in[12];
    float* out = (float*)d_out;

    const int* row = ei;
    const int* col = ei + N_EDGES;

    int *p_cnt, *p_off, *p_cursor, *p_src, *p_gcur;
    float *p_dinv;
    __half *p_t, *p_hh;
    cudaGetSymbolAddress((void**)&p_cnt,    d_cnt);
    cudaGetSymbolAddress((void**)&p_off,    d_off);
    cudaGetSymbolAddress((void**)&p_cursor, d_cursor);
    cudaGetSymbolAddress((void**)&p_src,    d_src);
    cudaGetSymbolAddress((void**)&p_gcur,   d_gcur);
    cudaGetSymbolAddress((void**)&p_dinv,   d_dinv);
    cudaGetSymbolAddress((void**)&p_t,      d_t);
    cudaGetSymbolAddress((void**)&p_hh,     d_hh);

    const int SM128 = (128 * 128 + 128 * 128) * 2;   // 64 KB
    const int SM64  = (128 * 128 + 128 * 64) * 2;    // 48 KB
    cudaFuncSetAttribute((const void*)gemm_mma_kernel<128, true>,  cudaFuncAttributeMaxDynamicSharedMemorySize, SM128);
    cudaFuncSetAttribute((const void*)gemm_mma_kernel<128, false>, cudaFuncAttributeMaxDynamicSharedMemorySize, SM128);
    cudaFuncSetAttribute((const void*)gemm_mma_kernel<64, false>,  cudaFuncAttributeMaxDynamicSharedMemorySize, SM64);

    const int E2 = (N_EDGES / 2 + 255) / 256;
    const int GB = (N_NODES + 127) / 128;    // 391
    const int AGG_BLOCKS = (N_NODES + 7) / 8;

    // CSR build
    count_kernel<<<E2, 256>>>(col, p_cnt);                                            // 1
    assign_kernel<<<(N_NODES + 1023) / 1024, 1024>>>(p_cnt, p_off, p_cursor, p_dinv, p_gcur); // 2
    fill_kernel<<<E2, 256>>>(row, col, p_cursor, p_src);                              // 3

    gemm_mma_kernel<128, true><<<GB, 256, SM128>>>(x, W1, p_dinv, p_t);               // 4
    agg_kernel<128><<<AGG_BLOCKS, 256>>>(p_t, p_off, p_cnt, p_dinv, b1, p_hh, p_src); // 5
    gemm_mma_kernel<128, false><<<GB, 256, SM128>>>(p_hh, W2, p_dinv, p_t);           // 6 <- ncu
    agg_kernel<128><<<AGG_BLOCKS, 256>>>(p_t, p_off, p_cnt, p_dinv, b2, p_hh, p_src); // 7
    gemm_mma_kernel<64, false><<<GB, 256, SM64>>>(p_hh, W3, p_dinv, p_t);             // 8
    agg_kernel<64><<<AGG_BLOCKS, 256>>>(p_t, p_off, p_cnt, p_dinv, b3, p_hh, p_src);  // 9

    pool_mlp_kernel<<<N_GRAPHS, 256>>>(p_hh, batch, Wf1, bf1, Wf2, bf2, out, p_cnt, p_gcur); // 10
}